// round 3
// baseline (speedup 1.0000x reference)
#include <cuda_runtime.h>
#include <math.h>

// Problem constants
#define BB   16
#define CC   512
#define HWW  1024
#define NG   32
#define CPG  16
#define GSZ  (CPG*HWW)   // 16384 elements per (batch, group)

// Scratch (allocation-free rule: __device__ globals).
// g_hx is reused as the attention-output buffer: it is dead after the k/v
// GEMMs, and gemm_av runs strictly after them in stream order.
__device__ float g_hx[(size_t)BB*CC*HWW];
__device__ float g_hy[(size_t)BB*CC*HWW];
__device__ float g_q [(size_t)BB*CC*HWW];
__device__ float g_k [(size_t)BB*CC*HWW];
__device__ float g_v [(size_t)BB*CC*HWW];
__device__ float g_s [(size_t)BB*HWW*HWW];

// ---------------------------------------------------------------------------
// GroupNorm: one block per (batch, group). 256 threads reduce 16384 elements.
// ---------------------------------------------------------------------------
__global__ void gn_kernel(const float* __restrict__ x, const float* __restrict__ sc,
                          const float* __restrict__ bi, float* __restrict__ out)
{
    __shared__ float shs[8], shq[8], shm[2];
    int bg = blockIdx.x;
    int b = bg >> 5;
    int g = bg & 31;
    const float* xp = x   + ((size_t)b*CC + (size_t)g*CPG)*HWW;
    float*       op = out + ((size_t)b*CC + (size_t)g*CPG)*HWW;
    int t = threadIdx.x;

    float s = 0.f, sq = 0.f;
    for (int i = t; i < GSZ; i += 256) {
        float v = xp[i];
        s += v; sq += v*v;
    }
    #pragma unroll
    for (int o = 16; o > 0; o >>= 1) {
        s  += __shfl_xor_sync(0xffffffffu, s,  o);
        sq += __shfl_xor_sync(0xffffffffu, sq, o);
    }
    if ((t & 31) == 0) { shs[t >> 5] = s; shq[t >> 5] = sq; }
    __syncthreads();
    if (t == 0) {
        float S = 0.f, Q = 0.f;
        #pragma unroll
        for (int i = 0; i < 8; i++) { S += shs[i]; Q += shq[i]; }
        float mean = S * (1.f / GSZ);
        float var  = Q * (1.f / GSZ) - mean * mean;
        shm[0] = mean;
        shm[1] = rsqrtf(var + 1e-6f);
    }
    __syncthreads();
    float mean = shm[0], rs = shm[1];
    for (int i = t; i < GSZ; i += 256) {
        int c = g*CPG + (i >> 10);
        op[i] = (xp[i] - mean) * rs * __ldg(&sc[c]) + __ldg(&bi[c]);
    }
}

// ---------------------------------------------------------------------------
// GEMM common config: 128x128 tile, K-slice 8, 256 threads, 8x8 microtile.
// Smem tiles padded to 132 floats/row: transposed scatter-stores and float4
// compute reads are both bank-conflict-free (132 mod 32 = 4 => bank 4k+m).
// ---------------------------------------------------------------------------

// C[o,n] = sum_c W[o,c] * X[b,c,n] + bias[o]  (+ optional residual), per batch
template<bool RES>
__global__ __launch_bounds__(256, 2)
void gemm_wx(const float* __restrict__ W, const float* __restrict__ X,
             const float* __restrict__ bias, const float* __restrict__ resid,
             float* __restrict__ Cout)
{
    __shared__ float As[8][132];
    __shared__ float Bs[8][132];
    int b = blockIdx.z;
    const float* Xb = X    + (size_t)b*CC*HWW;
    float*       Cb = Cout + (size_t)b*CC*HWW;
    int m0 = blockIdx.y * 128, n0 = blockIdx.x * 128;
    int t  = threadIdx.x;
    int tx = t & 15, ty = t >> 4;
    int m_a = t >> 1, k_a = (t & 1) * 4;      // A (W) transposed load
    int k_b = t >> 5, n_b = (t & 31) * 4;     // B (X) direct load

    float acc[8][8];
    #pragma unroll
    for (int i = 0; i < 8; i++)
        #pragma unroll
        for (int j = 0; j < 8; j++) acc[i][j] = 0.f;

    for (int k0 = 0; k0 < CC; k0 += 8) {
        float4 av = *(const float4*)&W [(size_t)(m0 + m_a)*CC  + k0 + k_a];
        float4 bv = *(const float4*)&Xb[(size_t)(k0 + k_b)*HWW + n0 + n_b];
        __syncthreads();
        As[k_a+0][m_a] = av.x; As[k_a+1][m_a] = av.y;
        As[k_a+2][m_a] = av.z; As[k_a+3][m_a] = av.w;
        *(float4*)&Bs[k_b][n_b] = bv;
        __syncthreads();
        #pragma unroll
        for (int kk = 0; kk < 8; kk++) {
            float a[8], bb2[8];
            *(float4*)(a)     = *(const float4*)&As[kk][ty*4];
            *(float4*)(a+4)   = *(const float4*)&As[kk][64 + ty*4];
            *(float4*)(bb2)   = *(const float4*)&Bs[kk][tx*4];
            *(float4*)(bb2+4) = *(const float4*)&Bs[kk][64 + tx*4];
            #pragma unroll
            for (int i = 0; i < 8; i++)
                #pragma unroll
                for (int j = 0; j < 8; j++) acc[i][j] += a[i] * bb2[j];
        }
    }

    #pragma unroll
    for (int ih = 0; ih < 2; ih++)
        #pragma unroll
        for (int ii = 0; ii < 4; ii++) {
            int i = ih*4 + ii;
            int m = m0 + ih*64 + ty*4 + ii;
            float bsv = __ldg(&bias[m]);
            #pragma unroll
            for (int jh = 0; jh < 2; jh++) {
                int n = n0 + jh*64 + tx*4;
                float4 r;
                r.x = acc[i][jh*4+0] + bsv;
                r.y = acc[i][jh*4+1] + bsv;
                r.z = acc[i][jh*4+2] + bsv;
                r.w = acc[i][jh*4+3] + bsv;
                if (RES) {
                    float4 xv = *(const float4*)&resid[(size_t)b*CC*HWW + (size_t)m*HWW + n];
                    r.x += xv.x; r.y += xv.y; r.z += xv.z; r.w += xv.w;
                }
                *(float4*)&Cb[(size_t)m*HWW + n] = r;
            }
        }
}

// S[i,j] = scale * sum_c q[b,c,i] * k[b,c,j]   (both operands K-major in memory)
__global__ __launch_bounds__(256, 2)
void gemm_qk(const float* __restrict__ Q, const float* __restrict__ Kt,
             float* __restrict__ S)
{
    __shared__ float As[8][132];
    __shared__ float Bs[8][132];
    int b = blockIdx.z;
    const float* Qb = Q  + (size_t)b*CC*HWW;
    const float* Kb = Kt + (size_t)b*CC*HWW;
    float*       Sb = S  + (size_t)b*HWW*HWW;
    int m0 = blockIdx.y * 128, n0 = blockIdx.x * 128;
    int t  = threadIdx.x;
    int tx = t & 15, ty = t >> 4;
    int k_l = t >> 5, v_l = (t & 31) * 4;

    float acc[8][8];
    #pragma unroll
    for (int i = 0; i < 8; i++)
        #pragma unroll
        for (int j = 0; j < 8; j++) acc[i][j] = 0.f;

    for (int k0 = 0; k0 < CC; k0 += 8) {
        float4 av = *(const float4*)&Qb[(size_t)(k0 + k_l)*HWW + m0 + v_l];
        float4 bv = *(const float4*)&Kb[(size_t)(k0 + k_l)*HWW + n0 + v_l];
        __syncthreads();
        *(float4*)&As[k_l][v_l] = av;
        *(float4*)&Bs[k_l][v_l] = bv;
        __syncthreads();
        #pragma unroll
        for (int kk = 0; kk < 8; kk++) {
            float a[8], bb2[8];
            *(float4*)(a)     = *(const float4*)&As[kk][ty*4];
            *(float4*)(a+4)   = *(const float4*)&As[kk][64 + ty*4];
            *(float4*)(bb2)   = *(const float4*)&Bs[kk][tx*4];
            *(float4*)(bb2+4) = *(const float4*)&Bs[kk][64 + tx*4];
            #pragma unroll
            for (int i = 0; i < 8; i++)
                #pragma unroll
                for (int j = 0; j < 8; j++) acc[i][j] += a[i] * bb2[j];
        }
    }

    const float scale = 0.044194173824159216f;  // 512^-0.5
    #pragma unroll
    for (int ih = 0; ih < 2; ih++)
        #pragma unroll
        for (int ii = 0; ii < 4; ii++) {
            int i = ih*4 + ii;
            int m = m0 + ih*64 + ty*4 + ii;
            #pragma unroll
            for (int jh = 0; jh < 2; jh++) {
                int n = n0 + jh*64 + tx*4;
                float4 r;
                r.x = acc[i][jh*4+0] * scale;
                r.y = acc[i][jh*4+1] * scale;
                r.z = acc[i][jh*4+2] * scale;
                r.w = acc[i][jh*4+3] * scale;
                *(float4*)&Sb[(size_t)m*HWW + n] = r;
            }
        }
}

// O[c,i] = sum_j v[b,c,j] * S[b,i,j]  (both operands contiguous in j = K dim)
__global__ __launch_bounds__(256, 2)
void gemm_av(const float* __restrict__ V, const float* __restrict__ S,
             float* __restrict__ O)
{
    __shared__ float As[8][132];
    __shared__ float Bs[8][132];
    int b = blockIdx.z;
    const float* Vb = V + (size_t)b*CC*HWW;
    const float* Sb = S + (size_t)b*HWW*HWW;
    float*       Ob = O + (size_t)b*CC*HWW;
    int m0 = blockIdx.y * 128, n0 = blockIdx.x * 128;
    int t  = threadIdx.x;
    int tx = t & 15, ty = t >> 4;
    int r_l = t >> 1, k_l = (t & 1) * 4;   // both operands transposed-scatter

    float acc[8][8];
    #pragma unroll
    for (int i = 0; i < 8; i++)
        #pragma unroll
        for (int j = 0; j < 8; j++) acc[i][j] = 0.f;

    for (int k0 = 0; k0 < HWW; k0 += 8) {
        float4 av = *(const float4*)&Vb[(size_t)(m0 + r_l)*HWW + k0 + k_l];
        float4 bv = *(const float4*)&Sb[(size_t)(n0 + r_l)*HWW + k0 + k_l];
        __syncthreads();
        As[k_l+0][r_l] = av.x; As[k_l+1][r_l] = av.y;
        As[k_l+2][r_l] = av.z; As[k_l+3][r_l] = av.w;
        Bs[k_l+0][r_l] = bv.x; Bs[k_l+1][r_l] = bv.y;
        Bs[k_l+2][r_l] = bv.z; Bs[k_l+3][r_l] = bv.w;
        __syncthreads();
        #pragma unroll
        for (int kk = 0; kk < 8; kk++) {
            float a[8], bb2[8];
            *(float4*)(a)     = *(const float4*)&As[kk][ty*4];
            *(float4*)(a+4)   = *(const float4*)&As[kk][64 + ty*4];
            *(float4*)(bb2)   = *(const float4*)&Bs[kk][tx*4];
            *(float4*)(bb2+4) = *(const float4*)&Bs[kk][64 + tx*4];
            #pragma unroll
            for (int i = 0; i < 8; i++)
                #pragma unroll
                for (int j = 0; j < 8; j++) acc[i][j] += a[i] * bb2[j];
        }
    }

    #pragma unroll
    for (int ih = 0; ih < 2; ih++)
        #pragma unroll
        for (int ii = 0; ii < 4; ii++) {
            int i = ih*4 + ii;
            int m = m0 + ih*64 + ty*4 + ii;
            #pragma unroll
            for (int jh = 0; jh < 2; jh++) {
                int n = n0 + jh*64 + tx*4;
                float4 r;
                r.x = acc[i][jh*4+0];
                r.y = acc[i][jh*4+1];
                r.z = acc[i][jh*4+2];
                r.w = acc[i][jh*4+3];
                *(float4*)&Ob[(size_t)m*HWW + n] = r;
            }
        }
}

// ---------------------------------------------------------------------------
// Row softmax over 1024 elements; register-resident (one gmem read + write).
// ---------------------------------------------------------------------------
__global__ void softmax_kernel(float* __restrict__ S)
{
    __shared__ float sh[8];
    size_t row = blockIdx.x;
    float* p = S + row * HWW;
    int t = threadIdx.x;

    float4 v = ((const float4*)p)[t];
    float m = fmaxf(fmaxf(v.x, v.y), fmaxf(v.z, v.w));
    #pragma unroll
    for (int o = 16; o > 0; o >>= 1) m = fmaxf(m, __shfl_xor_sync(0xffffffffu, m, o));
    if ((t & 31) == 0) sh[t >> 5] = m;
    __syncthreads();
    float M = sh[0];
    #pragma unroll
    for (int i = 1; i < 8; i++) M = fmaxf(M, sh[i]);
    __syncthreads();

    v.x = __expf(v.x - M); v.y = __expf(v.y - M);
    v.z = __expf(v.z - M); v.w = __expf(v.w - M);
    float s = v.x + v.y + v.z + v.w;
    #pragma unroll
    for (int o = 16; o > 0; o >>= 1) s += __shfl_xor_sync(0xffffffffu, s, o);
    if ((t & 31) == 0) sh[t >> 5] = s;
    __syncthreads();
    float T = 0.f;
    #pragma unroll
    for (int i = 0; i < 8; i++) T += sh[i];
    float inv = 1.0f / T;

    v.x *= inv; v.y *= inv; v.z *= inv; v.w *= inv;
    ((float4*)p)[t] = v;
}

// ---------------------------------------------------------------------------
// Launch: GN(x), GN(y) -> q,k,v GEMMs -> q^T k -> softmax -> v@attn^T -> proj+res
// ---------------------------------------------------------------------------
extern "C" void kernel_launch(void* const* d_in, const int* in_sizes, int n_in,
                              void* d_out, int out_size)
{
    const float* x   = (const float*)d_in[0];
    const float* y   = (const float*)d_in[1];
    const float* ns  = (const float*)d_in[2];
    const float* nb  = (const float*)d_in[3];
    const float* n1s = (const float*)d_in[4];
    const float* n1b = (const float*)d_in[5];
    const float* wq  = (const float*)d_in[6];
    const float* bq  = (const float*)d_in[7];
    const float* wk  = (const float*)d_in[8];
    const float* bk  = (const float*)d_in[9];
    const float* wv  = (const float*)d_in[10];
    const float* bv  = (const float*)d_in[11];
    const float* wp  = (const float*)d_in[12];
    const float* bp  = (const float*)d_in[13];
    float* out = (float*)d_out;

    float *hx, *hy, *q, *k, *v, *s;
    cudaGetSymbolAddress((void**)&hx, g_hx);
    cudaGetSymbolAddress((void**)&hy, g_hy);
    cudaGetSymbolAddress((void**)&q,  g_q);
    cudaGetSymbolAddress((void**)&k,  g_k);
    cudaGetSymbolAddress((void**)&v,  g_v);
    cudaGetSymbolAddress((void**)&s,  g_s);
    float* o = hx;   // alias: hx is dead after the k/v GEMMs complete

    gn_kernel<<<BB*NG, 256>>>(x, ns,  nb,  hx);
    gn_kernel<<<BB*NG, 256>>>(y, n1s, n1b, hy);

    dim3 gwx(HWW/128, CC/128, BB);     // (8, 4, 16)
    gemm_wx<false><<<gwx, 256>>>(wq, hy, bq, nullptr, q);
    gemm_wx<false><<<gwx, 256>>>(wk, hx, bk, nullptr, k);
    gemm_wx<false><<<gwx, 256>>>(wv, hx, bv, nullptr, v);

    dim3 gqk(HWW/128, HWW/128, BB);    // (8, 8, 16)
    gemm_qk<<<gqk, 256>>>(q, k, s);

    softmax_kernel<<<BB*HWW, 256>>>(s);

    gemm_av<<<gwx, 256>>>(v, s, o);

    gemm_wx<true><<<gwx, 256>>>(wp, o, bp, x, out);
}

// round 5
// speedup vs baseline: 2.8763x; 2.8763x over previous
#include <cuda_runtime.h>
#include <cstdint>
#include <math.h>

#define BB   16
#define CC   512
#define HWW  1024
#define ABUF ((size_t)BB*CC*HWW)      // 8M floats = 32MB

// Scratch (__device__ globals; no allocs allowed)
__device__ float g_hxT[ABUF];   // normalized x, [b][hw][c]; reused as O after k,v
__device__ float g_hyT[ABUF];   // normalized y, [b][hw][c]
__device__ float g_qT [ABUF];   // [b][hw][c]
__device__ float g_kT [ABUF];   // [b][hw][c]
__device__ float g_vT [ABUF];   // [b][hw][c]
__device__ float g_v2 [ABUF];   // [b][c][hw]
__device__ float g_s  [(size_t)BB*HWW*HWW];  // 64MB scores

__device__ __forceinline__ uint32_t smem_u32(const void* p) {
    uint32_t a;
    asm("{ .reg .u64 t; cvta.to.shared.u64 t, %1; cvt.u32.u64 %0, t; }" : "=r"(a) : "l"(p));
    return a;
}
#define CP_ASYNC16(sa, ga) \
    asm volatile("cp.async.cg.shared.global [%0], [%1], 16;" :: "r"(sa), "l"(ga) : "memory")
#define CP_COMMIT() asm volatile("cp.async.commit_group;" ::: "memory")
#define CP_WAIT1()  asm volatile("cp.async.wait_group 1;" ::: "memory")
#define CP_WAIT0()  asm volatile("cp.async.wait_group 0;" ::: "memory")

// ---------------------------------------------------------------------------
// tf32 mma.sync GEMM: D[m,n] = sum_k A[m,k]*B[n,k]; 128x128 block, K-chunk 32,
// double-buffered cp.async. 8 warps, warp tile 64x32 (4x4 m16n8k8 MMAs).
// Smem [128][36] pad: fragment LDS banks (4g+tg)%32 all-distinct.
// EPI: 0 = +bias[n] | 1 = *scale | 2 = none | 3 = +bias[m]+resid
// ---------------------------------------------------------------------------
template<int EPI>
__global__ __launch_bounds__(256, 2)
void mma_gemm(const float* __restrict__ A, const float* __restrict__ B,
              float* __restrict__ C, const float* __restrict__ bias,
              const float* __restrict__ resid,
              int NC, int lda, int ldb, int ldc,
              long aB, long bB, long cB, float scale)
{
    extern __shared__ float sm[];    // 2 stages x (A 128*36 + B 128*36)
    const int TP = 36, TILE = 128 * 36, STG = 2 * TILE;   // floats

    int t = threadIdx.x, lane = t & 31, w = t >> 5;
    int wr = w & 1, wc = w >> 1;          // warp grid 2 x 4
    int g = lane >> 2, tg = lane & 3;
    int bz = blockIdx.z, m0 = blockIdx.y * 128, n0 = blockIdx.x * 128;
    const float* Ab = A + (size_t)bz * aB;
    const float* Bb = B + (size_t)bz * bB;
    float*       Cb = C + (size_t)bz * cB;
    uint32_t smb = smem_u32(sm);

    auto load = [&](int c, int s) {
        int k0 = c * 32;
        #pragma unroll
        for (int j = 0; j < 4; j++) {
            int idx = t + 256 * j;          // 0..1023
            int r = idx >> 3, cq = (idx & 7) * 4;
            const float* ga = Ab + (size_t)(m0 + r) * lda + k0 + cq;
            const float* gb = Bb + (size_t)(n0 + r) * ldb + k0 + cq;
            uint32_t sa  = smb + (uint32_t)(s * STG + r * TP + cq) * 4u;
            uint32_t sbm = smb + (uint32_t)(s * STG + TILE + r * TP + cq) * 4u;
            CP_ASYNC16(sa, ga);
            CP_ASYNC16(sbm, gb);
        }
    };

    float acc[4][4][4];
    #pragma unroll
    for (int i = 0; i < 4; i++)
        #pragma unroll
        for (int j = 0; j < 4; j++)
            #pragma unroll
            for (int q = 0; q < 4; q++) acc[i][j][q] = 0.f;

    load(0, 0); CP_COMMIT();
    if (NC > 1) { load(1, 1); CP_COMMIT(); }

    for (int c = 0; c < NC; c++) {
        if (c + 1 < NC) CP_WAIT1(); else CP_WAIT0();
        __syncthreads();
        const float* As = sm + (c & 1) * STG;
        const float* Bs = As + TILE;
        #pragma unroll
        for (int kk = 0; kk < 32; kk += 8) {
            uint32_t af[4][4], bf[4][2];
            #pragma unroll
            for (int i = 0; i < 4; i++) {
                const float* ap = As + (size_t)(wr * 64 + i * 16 + g) * TP + kk + tg;
                af[i][0] = __float_as_uint(ap[0]);
                af[i][1] = __float_as_uint(ap[8 * TP]);
                af[i][2] = __float_as_uint(ap[4]);
                af[i][3] = __float_as_uint(ap[8 * TP + 4]);
            }
            #pragma unroll
            for (int j = 0; j < 4; j++) {
                const float* bp = Bs + (size_t)(wc * 32 + j * 8 + g) * TP + kk + tg;
                bf[j][0] = __float_as_uint(bp[0]);
                bf[j][1] = __float_as_uint(bp[4]);
            }
            #pragma unroll
            for (int i = 0; i < 4; i++)
                #pragma unroll
                for (int j = 0; j < 4; j++)
                    asm volatile(
                        "mma.sync.aligned.m16n8k8.row.col.f32.tf32.tf32.f32 "
                        "{%0,%1,%2,%3},{%4,%5,%6,%7},{%8,%9},{%0,%1,%2,%3};"
                        : "+f"(acc[i][j][0]), "+f"(acc[i][j][1]),
                          "+f"(acc[i][j][2]), "+f"(acc[i][j][3])
                        : "r"(af[i][0]), "r"(af[i][1]), "r"(af[i][2]), "r"(af[i][3]),
                          "r"(bf[j][0]), "r"(bf[j][1]));
        }
        __syncthreads();
        if (c + 2 < NC) { load(c + 2, c & 1); CP_COMMIT(); }
    }

    // Epilogue: acc[i][j] -> rows m0+wr*64+i*16+{g, g+8}, cols n0+wc*32+j*8+2*tg
    int mrow = m0 + wr * 64;
    int ncol = n0 + wc * 32;
    #pragma unroll
    for (int i = 0; i < 4; i++) {
        int r0 = mrow + i * 16 + g, r1 = r0 + 8;
        float bm0 = 0.f, bm1 = 0.f;
        if (EPI == 3) { bm0 = __ldg(&bias[r0]); bm1 = __ldg(&bias[r1]); }
        #pragma unroll
        for (int j = 0; j < 4; j++) {
            int cc = ncol + j * 8 + 2 * tg;
            float2 v0 = make_float2(acc[i][j][0], acc[i][j][1]);
            float2 v1 = make_float2(acc[i][j][2], acc[i][j][3]);
            if (EPI == 0) {
                float b0 = __ldg(&bias[cc]), b1 = __ldg(&bias[cc + 1]);
                v0.x += b0; v0.y += b1; v1.x += b0; v1.y += b1;
            } else if (EPI == 1) {
                v0.x *= scale; v0.y *= scale; v1.x *= scale; v1.y *= scale;
            } else if (EPI == 3) {
                const float* Rb = resid + (size_t)bz * cB;
                float2 x0 = *(const float2*)(Rb + (size_t)r0 * ldc + cc);
                float2 x1 = *(const float2*)(Rb + (size_t)r1 * ldc + cc);
                v0.x += bm0 + x0.x; v0.y += bm0 + x0.y;
                v1.x += bm1 + x1.x; v1.y += bm1 + x1.y;
            }
            *(float2*)(Cb + (size_t)r0 * ldc + cc) = v0;
            *(float2*)(Cb + (size_t)r1 * ldc + cc) = v1;
        }
    }
}

// ---------------------------------------------------------------------------
// GroupNorm with transposed output [b][hw][c]. One block per (b, group).
// ---------------------------------------------------------------------------
__global__ void gn_t_kernel(const float* __restrict__ x, const float* __restrict__ sc,
                            const float* __restrict__ bi, float* __restrict__ outT)
{
    extern __shared__ float xs[];      // 16 * 1026
    __shared__ float shs[8], shq[8], shm[2];
    int bg = blockIdx.x;
    int b = bg >> 5, g = bg & 31;
    const float* xp = x + ((size_t)b * CC + (size_t)g * 16) * HWW;
    int t = threadIdx.x;

    float s = 0.f, sq = 0.f;
    #pragma unroll 4
    for (int j = 0; j < 64; j++) {
        int idx = t + 256 * j;               // idx = c*1024 + hw
        float v = xp[idx];
        xs[(idx >> 10) * 1026 + (idx & 1023)] = v;
        s += v; sq += v * v;
    }
    #pragma unroll
    for (int o = 16; o > 0; o >>= 1) {
        s  += __shfl_xor_sync(0xffffffffu, s,  o);
        sq += __shfl_xor_sync(0xffffffffu, sq, o);
    }
    if ((t & 31) == 0) { shs[t >> 5] = s; shq[t >> 5] = sq; }
    __syncthreads();
    if (t == 0) {
        float S = 0.f, Q = 0.f;
        #pragma unroll
        for (int i = 0; i < 8; i++) { S += shs[i]; Q += shq[i]; }
        float mean = S * (1.f / 16384.f);
        float var  = Q * (1.f / 16384.f) - mean * mean;
        shm[0] = mean;
        shm[1] = rsqrtf(var + 1e-6f);
    }
    __syncthreads();
    float mean = shm[0], rs = shm[1];
    int cl = t & 15;
    float scv = __ldg(&sc[g * 16 + cl]) * rs;
    float biv = __ldg(&bi[g * 16 + cl]);
    float* op = outT + (size_t)b * HWW * CC + g * 16;
    #pragma unroll 4
    for (int j = 0; j < 64; j++) {
        int idx = t + 256 * j;
        int hw = idx >> 4;
        op[(size_t)hw * CC + cl] = (xs[cl * 1026 + hw] - mean) * scv + biv;
    }
}

// ---------------------------------------------------------------------------
// 32x32 tiled transpose: vT [b][hw][c] -> v2 [b][c][hw]
// ---------------------------------------------------------------------------
__global__ void transpose_kernel(const float* __restrict__ vT, float* __restrict__ v2)
{
    __shared__ float ts[32][33];
    int b = blockIdx.z;
    int hw0 = blockIdx.x * 32, c0 = blockIdx.y * 32;
    const float* src = vT + (size_t)b * CC * HWW;
    float*       dst = v2 + (size_t)b * CC * HWW;
    int t = threadIdx.x, tx = t & 31, ty = t >> 5;
    #pragma unroll
    for (int i = 0; i < 4; i++) {
        int hw = hw0 + ty + i * 8;
        ts[ty + i * 8][tx] = src[(size_t)hw * CC + c0 + tx];
    }
    __syncthreads();
    #pragma unroll
    for (int i = 0; i < 4; i++) {
        int c = c0 + ty + i * 8;
        dst[(size_t)c * HWW + hw0 + tx] = ts[tx][ty + i * 8];
    }
}

// ---------------------------------------------------------------------------
// Row softmax over 1024
// ---------------------------------------------------------------------------
__global__ void softmax_kernel(float* __restrict__ S)
{
    __shared__ float sh[8];
    size_t row = blockIdx.x;
    float* p = S + row * HWW;
    int t = threadIdx.x;

    float4 v = ((const float4*)p)[t];
    float m = fmaxf(fmaxf(v.x, v.y), fmaxf(v.z, v.w));
    #pragma unroll
    for (int o = 16; o > 0; o >>= 1) m = fmaxf(m, __shfl_xor_sync(0xffffffffu, m, o));
    if ((t & 31) == 0) sh[t >> 5] = m;
    __syncthreads();
    float M = sh[0];
    #pragma unroll
    for (int i = 1; i < 8; i++) M = fmaxf(M, sh[i]);
    __syncthreads();

    v.x = __expf(v.x - M); v.y = __expf(v.y - M);
    v.z = __expf(v.z - M); v.w = __expf(v.w - M);
    float s = v.x + v.y + v.z + v.w;
    #pragma unroll
    for (int o = 16; o > 0; o >>= 1) s += __shfl_xor_sync(0xffffffffu, s, o);
    if ((t & 31) == 0) sh[t >> 5] = s;
    __syncthreads();
    float T = 0.f;
    #pragma unroll
    for (int i = 0; i < 8; i++) T += sh[i];
    float inv = 1.0f / T;

    v.x *= inv; v.y *= inv; v.z *= inv; v.w *= inv;
    ((float4*)p)[t] = v;
}

// ---------------------------------------------------------------------------
extern "C" void kernel_launch(void* const* d_in, const int* in_sizes, int n_in,
                              void* d_out, int out_size)
{
    const float* x   = (const float*)d_in[0];
    const float* y   = (const float*)d_in[1];
    const float* ns  = (const float*)d_in[2];
    const float* nb  = (const float*)d_in[3];
    const float* n1s = (const float*)d_in[4];
    const float* n1b = (const float*)d_in[5];
    const float* wq  = (const float*)d_in[6];
    const float* bq  = (const float*)d_in[7];
    const float* wk  = (const float*)d_in[8];
    const float* bk  = (const float*)d_in[9];
    const float* wv  = (const float*)d_in[10];
    const float* bv  = (const float*)d_in[11];
    const float* wp  = (const float*)d_in[12];
    const float* bp  = (const float*)d_in[13];
    float* out = (float*)d_out;

    float *hxT, *hyT, *qT, *kT, *vT, *v2, *s;
    cudaGetSymbolAddress((void**)&hxT, g_hxT);
    cudaGetSymbolAddress((void**)&hyT, g_hyT);
    cudaGetSymbolAddress((void**)&qT,  g_qT);
    cudaGetSymbolAddress((void**)&kT,  g_kT);
    cudaGetSymbolAddress((void**)&vT,  g_vT);
    cudaGetSymbolAddress((void**)&v2,  g_v2);
    cudaGetSymbolAddress((void**)&s,   g_s);
    float* O = hxT;   // hxT dead after k,v GEMMs

    const int SMEM_GEMM = 4 * 128 * 36 * 4;          // 73728 B
    const int SMEM_GN   = 16 * 1026 * sizeof(float); // 65664 B
    cudaFuncSetAttribute(mma_gemm<0>, cudaFuncAttributeMaxDynamicSharedMemorySize, SMEM_GEMM);
    cudaFuncSetAttribute(mma_gemm<1>, cudaFuncAttributeMaxDynamicSharedMemorySize, SMEM_GEMM);
    cudaFuncSetAttribute(mma_gemm<2>, cudaFuncAttributeMaxDynamicSharedMemorySize, SMEM_GEMM);
    cudaFuncSetAttribute(mma_gemm<3>, cudaFuncAttributeMaxDynamicSharedMemorySize, SMEM_GEMM);
    cudaFuncSetAttribute(gn_t_kernel, cudaFuncAttributeMaxDynamicSharedMemorySize, SMEM_GN);

    const long AS = (long)CC * HWW;
    const long SS = (long)HWW * HWW;
    const float qkscale = 0.044194173824159216f;   // 512^-0.5

    gn_t_kernel<<<BB * 32, 256, SMEM_GN>>>(x, ns,  nb,  hxT);
    gn_t_kernel<<<BB * 32, 256, SMEM_GN>>>(y, n1s, n1b, hyT);

    // q/k/v: D[hw, oc] = sum_c actT[hw,c] * W[oc,c] + b[oc]
    dim3 gqkv(CC / 128, HWW / 128, BB);   // (4, 8, 16)
    mma_gemm<0><<<gqkv, 256, SMEM_GEMM>>>(hyT, wq, qT, bq, nullptr, 16, CC, CC, CC, AS, 0, AS, 0.f);
    mma_gemm<0><<<gqkv, 256, SMEM_GEMM>>>(hxT, wk, kT, bk, nullptr, 16, CC, CC, CC, AS, 0, AS, 0.f);
    mma_gemm<0><<<gqkv, 256, SMEM_GEMM>>>(hxT, wv, vT, bv, nullptr, 16, CC, CC, CC, AS, 0, AS, 0.f);

    transpose_kernel<<<dim3(HWW / 32, CC / 32, BB), 256>>>(vT, v2);

    // scores: S[i,j] = scale * sum_c qT[i,c] * kT[j,c]
    dim3 gqk(HWW / 128, HWW / 128, BB);   // (8, 8, 16)
    mma_gemm<1><<<gqk, 256, SMEM_GEMM>>>(qT, kT, s, nullptr, nullptr, 16, CC, CC, HWW, AS, AS, SS, qkscale);

    softmax_kernel<<<BB * HWW, 256>>>(s);

    // O[i, c] = sum_j attn[i,j] * v2[c,j]
    dim3 gav(CC / 128, HWW / 128, BB);    // (4, 8, 16)
    mma_gemm<2><<<gav, 256, SMEM_GEMM>>>(s, v2, O, nullptr, nullptr, 32, HWW, HWW, CC, SS, AS, AS, 0.f);

    // out[oc, hw] = sum_c wp[oc,c] * O[hw,c] + bp[oc] + x
    dim3 gproj(HWW / 128, CC / 128, BB);  // (8, 4, 16)
    mma_gemm<3><<<gproj, 256, SMEM_GEMM>>>(wp, O, out, bp, x, 16, CC, CC, HWW, 0, AS, AS, 0.f);
}